// round 10
// baseline (speedup 1.0000x reference)
#include <cuda_runtime.h>
#include <math.h>

#define HW 4096
#define WID 64

// Packed fp32x2 FMA (Blackwell FFMA2): d = a*b + d, lane-wise on 32-bit halves.
#define FMA2(d, a, b) asm("fma.rn.f32x2 %0, %1, %2, %0;" : "+l"(d) : "l"(a), "l"(b))

__device__ __forceinline__ float f2lo(unsigned long long v) {
    return __uint_as_float((unsigned)v);
}
__device__ __forceinline__ float f2hi(unsigned long long v) {
    return __uint_as_float((unsigned)(v >> 32));
}

// Scratch (allocation-free: device globals)
__device__ float g_qkv1[2 * 576 * 4096];   // after 1x1 conv
__device__ float g_qkv2[2 * 576 * 4096];   // after depthwise 3x3 (raw q,k,v — norm fused in natten)
__device__ float g_att [2 * 192 * 4096];   // attention output (channel = h*32+d)

// ---------------------------------------------------------------------------
// FFMA2 GEMM with bias: C[z] = A[M,K] @ B[z][K,N] + bias.
// BM=64 BN=128 BK=16, 256 threads, 4m x 8n outputs/thread as 16 f32x2 accs.
// ---------------------------------------------------------------------------
__global__ __launch_bounds__(256, 3)
void gemm_bias_kernel(const float* __restrict__ A,
                      const float* __restrict__ Bg,
                      const float* __restrict__ bias,
                      float* __restrict__ Cg,
                      int M, int K, int N)
{
    __shared__ alignas(16) float As[2][16][128];  // [k][2m],[2m+1] duplicated
    __shared__ alignas(16) float Bs[2][16][128];

    const int bN = blockIdx.x * 128;
    const int bM = blockIdx.y * 64;
    const float* Bp = Bg + (size_t)blockIdx.z * (size_t)K * N;
    float*       Cp = Cg + (size_t)blockIdx.z * (size_t)M * N;

    const int tid  = threadIdx.x;
    const int tcol = tid & 15;
    const int trow = tid >> 4;

    const int a_r = tid >> 2;
    const int a_c = (tid & 3) << 2;
    const int b_r = tid >> 4;
    const int b_c = (tid & 15) << 3;

    const float* aptr = A + (size_t)(bM + a_r) * K + a_c;
    const float* bptr = Bp + (size_t)b_r * N + bN + b_c;

    float4 av  = *reinterpret_cast<const float4*>(aptr);
    float4 bv0 = *reinterpret_cast<const float4*>(bptr);
    float4 bv1 = *reinterpret_cast<const float4*>(bptr + 4);

    unsigned long long acc[4][4];
#pragma unroll
    for (int i = 0; i < 4; i++)
#pragma unroll
        for (int p = 0; p < 4; p++) acc[i][p] = 0ull;

    *reinterpret_cast<float2*>(&As[0][a_c + 0][2 * a_r]) = make_float2(av.x, av.x);
    *reinterpret_cast<float2*>(&As[0][a_c + 1][2 * a_r]) = make_float2(av.y, av.y);
    *reinterpret_cast<float2*>(&As[0][a_c + 2][2 * a_r]) = make_float2(av.z, av.z);
    *reinterpret_cast<float2*>(&As[0][a_c + 3][2 * a_r]) = make_float2(av.w, av.w);
    *reinterpret_cast<float4*>(&Bs[0][b_r][b_c])     = bv0;
    *reinterpret_cast<float4*>(&Bs[0][b_r][b_c + 4]) = bv1;
    __syncthreads();

    int buf = 0;
    for (int k0 = 0; k0 < K; k0 += 16) {
        const bool more = (k0 + 16 < K);
        if (more) {
            av  = *reinterpret_cast<const float4*>(aptr + k0 + 16);
            bv0 = *reinterpret_cast<const float4*>(bptr + (size_t)(k0 + 16) * N);
            bv1 = *reinterpret_cast<const float4*>(bptr + (size_t)(k0 + 16) * N + 4);
        }
#pragma unroll
        for (int k = 0; k < 16; k++) {
            ulonglong2 adLo = *reinterpret_cast<const ulonglong2*>(&As[buf][k][trow * 8]);
            ulonglong2 adHi = *reinterpret_cast<const ulonglong2*>(&As[buf][k][trow * 8 + 4]);
            ulonglong2 bLo = *reinterpret_cast<const ulonglong2*>(&Bs[buf][k][tcol * 4]);
            ulonglong2 bHi = *reinterpret_cast<const ulonglong2*>(&Bs[buf][k][64 + tcol * 4]);

            FMA2(acc[0][0], adLo.x, bLo.x); FMA2(acc[0][1], adLo.x, bLo.y);
            FMA2(acc[0][2], adLo.x, bHi.x); FMA2(acc[0][3], adLo.x, bHi.y);
            FMA2(acc[1][0], adLo.y, bLo.x); FMA2(acc[1][1], adLo.y, bLo.y);
            FMA2(acc[1][2], adLo.y, bHi.x); FMA2(acc[1][3], adLo.y, bHi.y);
            FMA2(acc[2][0], adHi.x, bLo.x); FMA2(acc[2][1], adHi.x, bLo.y);
            FMA2(acc[2][2], adHi.x, bHi.x); FMA2(acc[2][3], adHi.x, bHi.y);
            FMA2(acc[3][0], adHi.y, bLo.x); FMA2(acc[3][1], adHi.y, bLo.y);
            FMA2(acc[3][2], adHi.y, bHi.x); FMA2(acc[3][3], adHi.y, bHi.y);
        }
        if (more) {
            const int nb = buf ^ 1;
            __syncthreads();
            *reinterpret_cast<float2*>(&As[nb][a_c + 0][2 * a_r]) = make_float2(av.x, av.x);
            *reinterpret_cast<float2*>(&As[nb][a_c + 1][2 * a_r]) = make_float2(av.y, av.y);
            *reinterpret_cast<float2*>(&As[nb][a_c + 2][2 * a_r]) = make_float2(av.z, av.z);
            *reinterpret_cast<float2*>(&As[nb][a_c + 3][2 * a_r]) = make_float2(av.w, av.w);
            *reinterpret_cast<float4*>(&Bs[nb][b_r][b_c])     = bv0;
            *reinterpret_cast<float4*>(&Bs[nb][b_r][b_c + 4]) = bv1;
            __syncthreads();
            buf = nb;
        }
    }

#pragma unroll
    for (int i = 0; i < 4; i++) {
        const int gm = bM + trow * 4 + i;
        const float bvi = bias[gm];
        float4 o0, o1;
        o0.x = f2lo(acc[i][0]) + bvi;
        o0.y = f2hi(acc[i][0]) + bvi;
        o0.z = f2lo(acc[i][1]) + bvi;
        o0.w = f2hi(acc[i][1]) + bvi;
        o1.x = f2lo(acc[i][2]) + bvi;
        o1.y = f2hi(acc[i][2]) + bvi;
        o1.z = f2lo(acc[i][3]) + bvi;
        o1.w = f2hi(acc[i][3]) + bvi;
        float* dst = Cp + (size_t)gm * N + bN;
        *reinterpret_cast<float4*>(dst + tcol * 4)      = o0;
        *reinterpret_cast<float4*>(dst + 64 + tcol * 4) = o1;
    }
}

// ---------------------------------------------------------------------------
// Split-K=2 FFMA2 GEMM, atomicAdd epilogue onto zeroed C.
// blockIdx.z = batch*2 + ksplit. Bias added by ksplit==0 half.
// Deterministic: exactly 2 fp32 partials per element (a+b commutes).
// ---------------------------------------------------------------------------
__global__ __launch_bounds__(256, 3)
void gemm_bias_splitk_kernel(const float* __restrict__ A,
                             const float* __restrict__ Bg,
                             const float* __restrict__ bias,
                             float* __restrict__ Cg,
                             int M, int K, int N)
{
    __shared__ alignas(16) float As[2][16][128];
    __shared__ alignas(16) float Bs[2][16][128];

    const int bN = blockIdx.x * 128;
    const int bM = blockIdx.y * 64;
    const int z  = blockIdx.z;
    const int zb = z >> 1;     // batch
    const int ks = z & 1;      // k-half
    const int KH = K >> 1;

    const float* Bp = Bg + (size_t)zb * (size_t)K * N;
    float*       Cp = Cg + (size_t)zb * (size_t)M * N;

    const int tid  = threadIdx.x;
    const int tcol = tid & 15;
    const int trow = tid >> 4;

    const int a_r = tid >> 2;
    const int a_c = (tid & 3) << 2;
    const int b_r = tid >> 4;
    const int b_c = (tid & 15) << 3;

    const float* aptr = A + (size_t)(bM + a_r) * K + ks * KH + a_c;
    const float* bptr = Bp + (size_t)(ks * KH + b_r) * N + bN + b_c;

    float4 av  = *reinterpret_cast<const float4*>(aptr);
    float4 bv0 = *reinterpret_cast<const float4*>(bptr);
    float4 bv1 = *reinterpret_cast<const float4*>(bptr + 4);

    unsigned long long acc[4][4];
#pragma unroll
    for (int i = 0; i < 4; i++)
#pragma unroll
        for (int p = 0; p < 4; p++) acc[i][p] = 0ull;

    *reinterpret_cast<float2*>(&As[0][a_c + 0][2 * a_r]) = make_float2(av.x, av.x);
    *reinterpret_cast<float2*>(&As[0][a_c + 1][2 * a_r]) = make_float2(av.y, av.y);
    *reinterpret_cast<float2*>(&As[0][a_c + 2][2 * a_r]) = make_float2(av.z, av.z);
    *reinterpret_cast<float2*>(&As[0][a_c + 3][2 * a_r]) = make_float2(av.w, av.w);
    *reinterpret_cast<float4*>(&Bs[0][b_r][b_c])     = bv0;
    *reinterpret_cast<float4*>(&Bs[0][b_r][b_c + 4]) = bv1;
    __syncthreads();

    int buf = 0;
    for (int k0 = 0; k0 < KH; k0 += 16) {
        const bool more = (k0 + 16 < KH);
        if (more) {
            av  = *reinterpret_cast<const float4*>(aptr + k0 + 16);
            bv0 = *reinterpret_cast<const float4*>(bptr + (size_t)(k0 + 16) * N);
            bv1 = *reinterpret_cast<const float4*>(bptr + (size_t)(k0 + 16) * N + 4);
        }
#pragma unroll
        for (int k = 0; k < 16; k++) {
            ulonglong2 adLo = *reinterpret_cast<const ulonglong2*>(&As[buf][k][trow * 8]);
            ulonglong2 adHi = *reinterpret_cast<const ulonglong2*>(&As[buf][k][trow * 8 + 4]);
            ulonglong2 bLo = *reinterpret_cast<const ulonglong2*>(&Bs[buf][k][tcol * 4]);
            ulonglong2 bHi = *reinterpret_cast<const ulonglong2*>(&Bs[buf][k][64 + tcol * 4]);

            FMA2(acc[0][0], adLo.x, bLo.x); FMA2(acc[0][1], adLo.x, bLo.y);
            FMA2(acc[0][2], adLo.x, bHi.x); FMA2(acc[0][3], adLo.x, bHi.y);
            FMA2(acc[1][0], adLo.y, bLo.x); FMA2(acc[1][1], adLo.y, bLo.y);
            FMA2(acc[1][2], adLo.y, bHi.x); FMA2(acc[1][3], adLo.y, bHi.y);
            FMA2(acc[2][0], adHi.x, bLo.x); FMA2(acc[2][1], adHi.x, bLo.y);
            FMA2(acc[2][2], adHi.x, bHi.x); FMA2(acc[2][3], adHi.x, bHi.y);
            FMA2(acc[3][0], adHi.y, bLo.x); FMA2(acc[3][1], adHi.y, bLo.y);
            FMA2(acc[3][2], adHi.y, bHi.x); FMA2(acc[3][3], adHi.y, bHi.y);
        }
        if (more) {
            const int nb = buf ^ 1;
            __syncthreads();
            *reinterpret_cast<float2*>(&As[nb][a_c + 0][2 * a_r]) = make_float2(av.x, av.x);
            *reinterpret_cast<float2*>(&As[nb][a_c + 1][2 * a_r]) = make_float2(av.y, av.y);
            *reinterpret_cast<float2*>(&As[nb][a_c + 2][2 * a_r]) = make_float2(av.z, av.z);
            *reinterpret_cast<float2*>(&As[nb][a_c + 3][2 * a_r]) = make_float2(av.w, av.w);
            *reinterpret_cast<float4*>(&Bs[nb][b_r][b_c])     = bv0;
            *reinterpret_cast<float4*>(&Bs[nb][b_r][b_c + 4]) = bv1;
            __syncthreads();
            buf = nb;
        }
    }

#pragma unroll
    for (int i = 0; i < 4; i++) {
        const int gm = bM + trow * 4 + i;
        const float bvi = (ks == 0) ? bias[gm] : 0.f;
        float* dst = Cp + (size_t)gm * N + bN;
        float v[8];
        v[0] = f2lo(acc[i][0]) + bvi;
        v[1] = f2hi(acc[i][0]) + bvi;
        v[2] = f2lo(acc[i][1]) + bvi;
        v[3] = f2hi(acc[i][1]) + bvi;
        v[4] = f2lo(acc[i][2]) + bvi;
        v[5] = f2hi(acc[i][2]) + bvi;
        v[6] = f2lo(acc[i][3]) + bvi;
        v[7] = f2hi(acc[i][3]) + bvi;
#pragma unroll
        for (int t = 0; t < 4; t++) atomicAdd(dst + tcol * 4 + t, v[t]);
#pragma unroll
        for (int t = 0; t < 4; t++) atomicAdd(dst + 64 + tcol * 4 + t, v[4 + t]);
    }
}

// ---------------------------------------------------------------------------
// Depthwise 3x3 SAME conv, smem-tiled: one block per (b,channel) 64x64 plane.
// 256 threads; thread -> row i = tid>>2, cols [c0, c0+16), c0 = (tid&3)*16.
// ---------------------------------------------------------------------------
#define DWS 68   // padded smem row stride

__global__ __launch_bounds__(256)
void dwconv_kernel(const float* __restrict__ in,
                   const float* __restrict__ w9,
                   const float* __restrict__ bias,
                   float* __restrict__ outp)
{
    __shared__ alignas(16) float s[64 * DWS];

    const int bc = blockIdx.x;          // b*576 + c
    const int c  = bc % 576;
    const int tid = threadIdx.x;

    const float4* src = reinterpret_cast<const float4*>(in + (size_t)bc * HW);
#pragma unroll
    for (int e = tid; e < 1024; e += 256) {
        float4 v = src[e];
        int r  = e >> 4;
        int cc = (e & 15) << 2;
        *reinterpret_cast<float4*>(&s[r * DWS + cc]) = v;
    }

    float wv[9];
#pragma unroll
    for (int t = 0; t < 9; t++) wv[t] = __ldg(&w9[c * 9 + t]);
    const float bv = __ldg(&bias[c]);
    __syncthreads();

    const int i  = tid >> 2;
    const int c0 = (tid & 3) << 4;

    float a[16];
#pragma unroll
    for (int t = 0; t < 16; t++) a[t] = bv;

#pragma unroll
    for (int di = 0; di < 3; di++) {
        const int ii = i + di - 1;
        if (ii < 0 || ii > 63) continue;
        const float* row = &s[ii * DWS];
        float r[18];
        r[0]  = (c0 == 0)  ? 0.f : row[c0 - 1];
        r[17] = (c0 == 48) ? 0.f : row[c0 + 16];
#pragma unroll
        for (int t = 0; t < 16; t++) r[t + 1] = row[c0 + t];
#pragma unroll
        for (int dj = 0; dj < 3; dj++) {
            const float wc = wv[di * 3 + dj];
#pragma unroll
            for (int t = 0; t < 16; t++) a[t] += wc * r[t + dj];
        }
    }

    float* dst = outp + (size_t)bc * HW + i * WID + c0;
#pragma unroll
    for (int t = 0; t < 4; t++)
        *reinterpret_cast<float4*>(dst + t * 4) =
            make_float4(a[t * 4], a[t * 4 + 1], a[t * 4 + 2], a[t * 4 + 3]);
}

// ---------------------------------------------------------------------------
// Neighborhood attention (7x7 clipped window), block = (8x8 pixel tile, head, b).
// L2-norm of q and K fused. FFMA2 for dot products and AV accumulation.
// ---------------------------------------------------------------------------
#define KVS 36
#define BFS 52

__global__ __launch_bounds__(256, 5)
void natten_kernel(const float* __restrict__ qkv,
                   const float* __restrict__ rpb,
                   const float* __restrict__ temp,
                   float* __restrict__ outp)
{
    const int h  = blockIdx.z % 6;
    const int b  = blockIdx.z / 6;
    const int i0 = blockIdx.y * 8;
    const int j0 = blockIdx.x * 8;
    const int r0 = min(max(i0 - 3, 0), 50);
    const int c0 = min(max(j0 - 3, 0), 50);

    __shared__ alignas(16) float kv_s[196 * KVS];
    __shared__ alignas(16) float buf [64 * BFS];
    __shared__ float rpb_s[169];

    const int tid  = threadIdx.x;
    const int lane = tid & 31;
    const int w    = tid >> 5;

    const float* qbase = qkv + (size_t)(b * 576 +       h * 32) * HW;
    const float* kbase = qkv + (size_t)(b * 576 + 192 + h * 32) * HW;
    const float* vbase = qkv + (size_t)(b * 576 + 384 + h * 32) * HW;

    for (int e = tid; e < 2048; e += 256) {
        int d  = e >> 6;
        int pi = (e >> 3) & 7;
        int pj = e & 7;
        buf[(pi * 8 + pj) * BFS + d] = qbase[(size_t)d * HW + (i0 + pi) * WID + (j0 + pj)];
    }
    for (int e = tid; e < 6272; e += 256) {
        int d = e / 196;
        int p = e % 196;
        kv_s[p * KVS + d] = kbase[(size_t)d * HW + (r0 + p / 14) * WID + (c0 + p % 14)];
    }
    for (int e = tid; e < 169; e += 256) rpb_s[e] = rpb[h * 169 + e];
    __syncthreads();

    if (tid < 196) {
        float4* r = reinterpret_cast<float4*>(&kv_s[tid * KVS]);
        float ss = 0.f;
#pragma unroll
        for (int t = 0; t < 8; t++) {
            float4 v = r[t];
            ss += v.x * v.x + v.y * v.y + v.z * v.z + v.w * v.w;
        }
        float sc = 1.f / fmaxf(sqrtf(ss), 1e-12f);
#pragma unroll
        for (int t = 0; t < 8; t++) {
            float4 v = r[t];
            r[t] = make_float4(v.x * sc, v.y * sc, v.z * sc, v.w * sc);
        }
    }
    if (tid < 64) {
        float4* r = reinterpret_cast<float4*>(&buf[tid * BFS]);
        float ss = 0.f;
#pragma unroll
        for (int t = 0; t < 8; t++) {
            float4 v = r[t];
            ss += v.x * v.x + v.y * v.y + v.z * v.z + v.w * v.w;
        }
        float sc = 1.f / fmaxf(sqrtf(ss), 1e-12f);
#pragma unroll
        for (int t = 0; t < 8; t++) {
            float4 v = r[t];
            r[t] = make_float4(v.x * sc, v.y * sc, v.z * sc, v.w * sc);
        }
    }
    __syncthreads();

    const int i  = i0 + w;
    const int si = min(max(i - 3, 0), 57);
    const float tscale = temp[h];

    const int ki1 = lane / 7, kj1 = lane % 7;
    const int ki2 = (lane + 32) / 7, kj2 = (lane + 32) % 7;
    const bool has2 = (lane < 17);

    const int rowBase = (si - r0) * 14;
    const int riOff   = si - i + 6;
    const int kOff1 = ki1 * 14 + kj1;
    const int kOff2 = ki2 * 14 + kj2;
    const int rb1   = (riOff + ki1) * 13 + kj1;
    const int rb2   = (riOff + ki2) * 13 + kj2;

#pragma unroll
    for (int px = 0; px < 8; px++) {
        const int j  = j0 + px;
        const int sj = min(max(j - 3, 0), 57);
        const int base  = rowBase + (sj - c0);
        const int cjOff = sj - j + 6;
        const int o1 = base + kOff1;
        const int o2 = has2 ? (base + kOff2) : 0;

        const ulonglong2* qp = reinterpret_cast<const ulonglong2*>(&buf[(w * 8 + px) * BFS]);
        const ulonglong2* k1 = reinterpret_cast<const ulonglong2*>(&kv_s[o1 * KVS]);
        const ulonglong2* k2 = reinterpret_cast<const ulonglong2*>(&kv_s[o2 * KVS]);

        unsigned long long s1p = 0ull, s2p = 0ull;
#pragma unroll
        for (int kd = 0; kd < 8; kd++) {
            ulonglong2 q2 = qp[kd];
            ulonglong2 a2 = k1[kd];
            ulonglong2 c2 = k2[kd];
            FMA2(s1p, q2.x, a2.x); FMA2(s1p, q2.y, a2.y);
            FMA2(s2p, q2.x, c2.x); FMA2(s2p, q2.y, c2.y);
        }
        float s1 = f2lo(s1p) + f2hi(s1p);
        float s2 = f2lo(s2p) + f2hi(s2p);

        s1 = (s1 + rpb_s[rb1 + cjOff]) * tscale;
        s2 = has2 ? (s2 + rpb_s[rb2 + cjOff]) * tscale : -1e30f;

        float m = fmaxf(s1, s2);
#pragma unroll
        for (int o = 16; o > 0; o >>= 1) m = fmaxf(m, __shfl_xor_sync(0xffffffffu, m, o));
        float e1 = __expf(s1 - m);
        float e2 = has2 ? __expf(s2 - m) : 0.f;
        float sm = e1 + e2;
#pragma unroll
        for (int o = 16; o > 0; o >>= 1) sm += __shfl_xor_sync(0xffffffffu, sm, o);
        float inv = 1.f / sm;
        buf[(w * 8 + px) * BFS + lane] = e1 * inv;
        if (has2) buf[(w * 8 + px) * BFS + lane + 32] = e2 * inv;
    }
    __syncthreads();

    for (int e = tid; e < 6272; e += 256) {
        int d = e / 196;
        int p = e % 196;
        kv_s[p * KVS + d] = vbase[(size_t)d * HW + (r0 + p / 14) * WID + (c0 + p % 14)];
    }
    __syncthreads();

    {
        const int oct = lane >> 3;
        const int dl  = lane & 7;
#pragma unroll
        for (int pass = 0; pass < 2; pass++) {
            const int px = pass * 4 + oct;
            const int j  = j0 + px;
            const int sj = min(max(j - 3, 0), 57);
            const int base = rowBase + (sj - c0);
            const float* pp = &buf[(w * 8 + px) * BFS];

            unsigned long long acc0 = 0ull, acc1 = 0ull;
            const float* vrow = &kv_s[base * KVS];
            int n = 0;
#pragma unroll
            for (int ki = 0; ki < 7; ki++) {
#pragma unroll
                for (int kj = 0; kj < 7; kj++) {
                    float p = pp[n++];
                    unsigned long long pd;
                    asm("mov.b64 %0, {%1, %1};" : "=l"(pd) : "f"(p));
                    ulonglong2 v2 = reinterpret_cast<const ulonglong2*>(vrow + kj * KVS)[dl];
                    FMA2(acc0, pd, v2.x);
                    FMA2(acc1, pd, v2.y);
                }
                vrow += 14 * KVS;
            }
            float4 o;
            o.x = f2lo(acc0); o.y = f2hi(acc0);
            o.z = f2lo(acc1); o.w = f2hi(acc1);
            reinterpret_cast<float4*>(&buf[(w * 8 + px) * BFS])[dl] = o;
        }
    }
    __syncthreads();

    for (int e = tid; e < 2048; e += 256) {
        int d  = e >> 6;
        int pi = (e >> 3) & 7;
        int pj = e & 7;
        outp[(size_t)(b * 192 + h * 32 + d) * HW + (i0 + pi) * WID + (j0 + pj)] =
            buf[(pi * 8 + pj) * BFS + d];
    }
}

// ---------------------------------------------------------------------------
extern "C" void kernel_launch(void* const* d_in, const int* in_sizes, int n_in,
                              void* d_out, int out_size)
{
    const float* x    = (const float*)d_in[0];
    const float* W1   = (const float*)d_in[1];
    const float* b1   = (const float*)d_in[2];
    const float* W2   = (const float*)d_in[3];
    const float* b2   = (const float*)d_in[4];
    const float* temp = (const float*)d_in[5];
    const float* rpb  = (const float*)d_in[6];
    const float* Wp   = (const float*)d_in[7];
    const float* bp   = (const float*)d_in[8];
    float* out = (float*)d_out;

    float *qkv1p, *qkv2p, *attp;
    cudaGetSymbolAddress((void**)&qkv1p, g_qkv1);
    cudaGetSymbolAddress((void**)&qkv2p, g_qkv2);
    cudaGetSymbolAddress((void**)&attp,  g_att);

    dim3 blk(256);

    // 1) qkv 1x1 conv: [576x192]@[192x4096] per batch
    gemm_bias_kernel<<<dim3(32, 9, 2), blk>>>(W1, x, b1, qkv1p, 576, 192, 4096);

    // 2) depthwise 3x3 (smem-tiled per plane)
    dwconv_kernel<<<1152, blk>>>(qkv1p, W2, b2, qkv2p);

    // 3) neighborhood attention (l2norm fused)
    natten_kernel<<<dim3(8, 8, 12), blk>>>(qkv2p, rpb, temp, attp);

    // 4) projection 1x1 conv: split-K=2 + atomic accumulate onto zeroed out
    cudaMemsetAsync(out, 0, (size_t)out_size * sizeof(float));
    gemm_bias_splitk_kernel<<<dim3(32, 3, 4), blk>>>(Wp, attp, bp, out, 192, 192, 4096);
}

// round 15
// speedup vs baseline: 1.1617x; 1.1617x over previous
#include <cuda_runtime.h>
#include <math.h>

#define HW 4096
#define WID 64

// Packed fp32x2 FMA (Blackwell FFMA2): d = a*b + d, lane-wise on 32-bit halves.
#define FMA2(d, a, b) asm("fma.rn.f32x2 %0, %1, %2, %0;" : "+l"(d) : "l"(a), "l"(b))
// Duplicate one fp32 into both halves of a 64-bit pair.
#define DUP2(d, f)    asm("mov.b64 %0, {%1, %1};" : "=l"(d) : "f"(f))

__device__ __forceinline__ float f2lo(unsigned long long v) {
    return __uint_as_float((unsigned)v);
}
__device__ __forceinline__ float f2hi(unsigned long long v) {
    return __uint_as_float((unsigned)(v >> 32));
}

// Scratch (allocation-free: device globals)
__device__ float g_qkv1[2 * 576 * 4096];   // after 1x1 conv
__device__ float g_qkv2[2 * 576 * 4096];   // after depthwise 3x3
__device__ float g_att [2 * 192 * 4096];   // attention output

// ---------------------------------------------------------------------------
// FFMA2 GEMM core: 128 threads, BM=64 BN=128 BK=16, 8m x 8n outputs/thread.
// Per k-step: 4 LDS.128 + 8 dup-MOV (alu pipe) + 32 FMA2 (64 MACs / 64B LDS).
// SPLITK: 0 = full-K direct store; 1 = split-K half with atomicAdd epilogue.
// ---------------------------------------------------------------------------
template <int SPLITK>
__device__ __forceinline__
void gemm_core(const float* __restrict__ A,
               const float* __restrict__ Bg,
               const float* __restrict__ bias,
               float* __restrict__ Cg,
               int M, int K, int N)
{
    __shared__ alignas(16) float As[2][16][64];
    __shared__ alignas(16) float Bs[2][16][128];

    const int bN = blockIdx.x * 128;
    const int bM = blockIdx.y * 64;

    int zb, ks, KH, kbase;
    if (SPLITK) {
        zb = blockIdx.z >> 1;
        ks = blockIdx.z & 1;
        KH = K >> 1;
        kbase = ks * KH;
    } else {
        zb = blockIdx.z;
        ks = 0;
        KH = K;
        kbase = 0;
    }

    const float* Bp = Bg + (size_t)zb * (size_t)K * N;
    float*       Cp = Cg + (size_t)zb * (size_t)M * N;

    const int tid  = threadIdx.x;
    const int tcol = tid & 15;   // 16 n-groups
    const int trow = tid >> 4;   // 8 m-groups of 8 rows

    // loaders
    const int a_r = tid >> 1;          // 0..63
    const int a_c = (tid & 1) << 3;    // 0 or 8
    const int b_r = tid >> 3;          // 0..15
    const int b_c = (tid & 7) << 4;    // 0..112

    const float* aptr = A + (size_t)(bM + a_r) * K + kbase + a_c;
    const float* bptr = Bp + (size_t)(kbase + b_r) * N + bN + b_c;

    float4 av0 = *reinterpret_cast<const float4*>(aptr);
    float4 av1 = *reinterpret_cast<const float4*>(aptr + 4);
    float4 bv0 = *reinterpret_cast<const float4*>(bptr);
    float4 bv1 = *reinterpret_cast<const float4*>(bptr + 4);
    float4 bv2 = *reinterpret_cast<const float4*>(bptr + 8);
    float4 bv3 = *reinterpret_cast<const float4*>(bptr + 12);

    unsigned long long acc[8][4];
#pragma unroll
    for (int i = 0; i < 8; i++)
#pragma unroll
        for (int p = 0; p < 4; p++) acc[i][p] = 0ull;

    // A stored transposed: As[k][m]
    As[0][a_c + 0][a_r] = av0.x;
    As[0][a_c + 1][a_r] = av0.y;
    As[0][a_c + 2][a_r] = av0.z;
    As[0][a_c + 3][a_r] = av0.w;
    As[0][a_c + 4][a_r] = av1.x;
    As[0][a_c + 5][a_r] = av1.y;
    As[0][a_c + 6][a_r] = av1.z;
    As[0][a_c + 7][a_r] = av1.w;
    *reinterpret_cast<float4*>(&Bs[0][b_r][b_c])      = bv0;
    *reinterpret_cast<float4*>(&Bs[0][b_r][b_c + 4])  = bv1;
    *reinterpret_cast<float4*>(&Bs[0][b_r][b_c + 8])  = bv2;
    *reinterpret_cast<float4*>(&Bs[0][b_r][b_c + 12]) = bv3;
    __syncthreads();

    int buf = 0;
    for (int k0 = 0; k0 < KH; k0 += 16) {
        const bool more = (k0 + 16 < KH);
        if (more) {
            av0 = *reinterpret_cast<const float4*>(aptr + k0 + 16);
            av1 = *reinterpret_cast<const float4*>(aptr + k0 + 20);
            bv0 = *reinterpret_cast<const float4*>(bptr + (size_t)(k0 + 16) * N);
            bv1 = *reinterpret_cast<const float4*>(bptr + (size_t)(k0 + 16) * N + 4);
            bv2 = *reinterpret_cast<const float4*>(bptr + (size_t)(k0 + 16) * N + 8);
            bv3 = *reinterpret_cast<const float4*>(bptr + (size_t)(k0 + 16) * N + 12);
        }
#pragma unroll
        for (int k = 0; k < 16; k++) {
            float4 aA = *reinterpret_cast<const float4*>(&As[buf][k][trow * 8]);
            float4 aB = *reinterpret_cast<const float4*>(&As[buf][k][trow * 8 + 4]);
            ulonglong2 bLo = *reinterpret_cast<const ulonglong2*>(&Bs[buf][k][tcol * 4]);
            ulonglong2 bHi = *reinterpret_cast<const ulonglong2*>(&Bs[buf][k][64 + tcol * 4]);

            unsigned long long ad;
            DUP2(ad, aA.x);
            FMA2(acc[0][0], ad, bLo.x); FMA2(acc[0][1], ad, bLo.y);
            FMA2(acc[0][2], ad, bHi.x); FMA2(acc[0][3], ad, bHi.y);
            DUP2(ad, aA.y);
            FMA2(acc[1][0], ad, bLo.x); FMA2(acc[1][1], ad, bLo.y);
            FMA2(acc[1][2], ad, bHi.x); FMA2(acc[1][3], ad, bHi.y);
            DUP2(ad, aA.z);
            FMA2(acc[2][0], ad, bLo.x); FMA2(acc[2][1], ad, bLo.y);
            FMA2(acc[2][2], ad, bHi.x); FMA2(acc[2][3], ad, bHi.y);
            DUP2(ad, aA.w);
            FMA2(acc[3][0], ad, bLo.x); FMA2(acc[3][1], ad, bLo.y);
            FMA2(acc[3][2], ad, bHi.x); FMA2(acc[3][3], ad, bHi.y);
            DUP2(ad, aB.x);
            FMA2(acc[4][0], ad, bLo.x); FMA2(acc[4][1], ad, bLo.y);
            FMA2(acc[4][2], ad, bHi.x); FMA2(acc[4][3], ad, bHi.y);
            DUP2(ad, aB.y);
            FMA2(acc[5][0], ad, bLo.x); FMA2(acc[5][1], ad, bLo.y);
            FMA2(acc[5][2], ad, bHi.x); FMA2(acc[5][3], ad, bHi.y);
            DUP2(ad, aB.z);
            FMA2(acc[6][0], ad, bLo.x); FMA2(acc[6][1], ad, bLo.y);
            FMA2(acc[6][2], ad, bHi.x); FMA2(acc[6][3], ad, bHi.y);
            DUP2(ad, aB.w);
            FMA2(acc[7][0], ad, bLo.x); FMA2(acc[7][1], ad, bLo.y);
            FMA2(acc[7][2], ad, bHi.x); FMA2(acc[7][3], ad, bHi.y);
        }
        if (more) {
            const int nb = buf ^ 1;
            __syncthreads();
            As[nb][a_c + 0][a_r] = av0.x;
            As[nb][a_c + 1][a_r] = av0.y;
            As[nb][a_c + 2][a_r] = av0.z;
            As[nb][a_c + 3][a_r] = av0.w;
            As[nb][a_c + 4][a_r] = av1.x;
            As[nb][a_c + 5][a_r] = av1.y;
            As[nb][a_c + 6][a_r] = av1.z;
            As[nb][a_c + 7][a_r] = av1.w;
            *reinterpret_cast<float4*>(&Bs[nb][b_r][b_c])      = bv0;
            *reinterpret_cast<float4*>(&Bs[nb][b_r][b_c + 4])  = bv1;
            *reinterpret_cast<float4*>(&Bs[nb][b_r][b_c + 8])  = bv2;
            *reinterpret_cast<float4*>(&Bs[nb][b_r][b_c + 12]) = bv3;
            __syncthreads();
            buf = nb;
        }
    }

#pragma unroll
    for (int i = 0; i < 8; i++) {
        const int gm = bM + trow * 8 + i;
        const float bvi = (ks == 0) ? bias[gm] : 0.f;
        float* dst = Cp + (size_t)gm * N + bN;
        if (SPLITK) {
            float v[8];
            v[0] = f2lo(acc[i][0]) + bvi;
            v[1] = f2hi(acc[i][0]) + bvi;
            v[2] = f2lo(acc[i][1]) + bvi;
            v[3] = f2hi(acc[i][1]) + bvi;
            v[4] = f2lo(acc[i][2]) + bvi;
            v[5] = f2hi(acc[i][2]) + bvi;
            v[6] = f2lo(acc[i][3]) + bvi;
            v[7] = f2hi(acc[i][3]) + bvi;
#pragma unroll
            for (int t = 0; t < 4; t++) atomicAdd(dst + tcol * 4 + t, v[t]);
#pragma unroll
            for (int t = 0; t < 4; t++) atomicAdd(dst + 64 + tcol * 4 + t, v[4 + t]);
        } else {
            float4 o0, o1;
            o0.x = f2lo(acc[i][0]) + bvi;
            o0.y = f2hi(acc[i][0]) + bvi;
            o0.z = f2lo(acc[i][1]) + bvi;
            o0.w = f2hi(acc[i][1]) + bvi;
            o1.x = f2lo(acc[i][2]) + bvi;
            o1.y = f2hi(acc[i][2]) + bvi;
            o1.z = f2lo(acc[i][3]) + bvi;
            o1.w = f2hi(acc[i][3]) + bvi;
            *reinterpret_cast<float4*>(dst + tcol * 4)      = o0;
            *reinterpret_cast<float4*>(dst + 64 + tcol * 4) = o1;
        }
    }
}

__global__ __launch_bounds__(128, 4)
void gemm_bias_kernel(const float* __restrict__ A, const float* __restrict__ Bg,
                      const float* __restrict__ bias, float* __restrict__ Cg,
                      int M, int K, int N)
{
    gemm_core<0>(A, Bg, bias, Cg, M, K, N);
}

__global__ __launch_bounds__(128, 4)
void gemm_bias_splitk_kernel(const float* __restrict__ A, const float* __restrict__ Bg,
                             const float* __restrict__ bias, float* __restrict__ Cg,
                             int M, int K, int N)
{
    gemm_core<1>(A, Bg, bias, Cg, M, K, N);
}

// ---------------------------------------------------------------------------
// Depthwise 3x3 SAME conv, smem-tiled: one block per (b,channel) 64x64 plane.
// ---------------------------------------------------------------------------
#define DWS 68

__global__ __launch_bounds__(256)
void dwconv_kernel(const float* __restrict__ in,
                   const float* __restrict__ w9,
                   const float* __restrict__ bias,
                   float* __restrict__ outp)
{
    __shared__ alignas(16) float s[64 * DWS];

    const int bc = blockIdx.x;
    const int c  = bc % 576;
    const int tid = threadIdx.x;

    const float4* src = reinterpret_cast<const float4*>(in + (size_t)bc * HW);
#pragma unroll
    for (int e = tid; e < 1024; e += 256) {
        float4 v = src[e];
        int r  = e >> 4;
        int cc = (e & 15) << 2;
        *reinterpret_cast<float4*>(&s[r * DWS + cc]) = v;
    }

    float wv[9];
#pragma unroll
    for (int t = 0; t < 9; t++) wv[t] = __ldg(&w9[c * 9 + t]);
    const float bv = __ldg(&bias[c]);
    __syncthreads();

    const int i  = tid >> 2;
    const int c0 = (tid & 3) << 4;

    float a[16];
#pragma unroll
    for (int t = 0; t < 16; t++) a[t] = bv;

#pragma unroll
    for (int di = 0; di < 3; di++) {
        const int ii = i + di - 1;
        if (ii < 0 || ii > 63) continue;
        const float* row = &s[ii * DWS];
        float r[18];
        r[0]  = (c0 == 0)  ? 0.f : row[c0 - 1];
        r[17] = (c0 == 48) ? 0.f : row[c0 + 16];
#pragma unroll
        for (int t = 0; t < 16; t++) r[t + 1] = row[c0 + t];
#pragma unroll
        for (int dj = 0; dj < 3; dj++) {
            const float wc = wv[di * 3 + dj];
#pragma unroll
            for (int t = 0; t < 16; t++) a[t] += wc * r[t + dj];
        }
    }

    float* dst = outp + (size_t)bc * HW + i * WID + c0;
#pragma unroll
    for (int t = 0; t < 4; t++)
        *reinterpret_cast<float4*>(dst + t * 4) =
            make_float4(a[t * 4], a[t * 4 + 1], a[t * 4 + 2], a[t * 4 + 3]);
}

// ---------------------------------------------------------------------------
// Neighborhood attention (7x7 clipped window), block = (8x8 pixel tile, head, b).
// ---------------------------------------------------------------------------
#define KVS 36
#define BFS 52

__global__ __launch_bounds__(256, 5)
void natten_kernel(const float* __restrict__ qkv,
                   const float* __restrict__ rpb,
                   const float* __restrict__ temp,
                   float* __restrict__ outp)
{
    const int h  = blockIdx.z % 6;
    const int b  = blockIdx.z / 6;
    const int i0 = blockIdx.y * 8;
    const int j0 = blockIdx.x * 8;
    const int r0 = min(max(i0 - 3, 0), 50);
    const int c0 = min(max(j0 - 3, 0), 50);

    __shared__ alignas(16) float kv_s[196 * KVS];
    __shared__ alignas(16) float buf [64 * BFS];
    __shared__ float rpb_s[169];

    const int tid  = threadIdx.x;
    const int lane = tid & 31;
    const int w    = tid >> 5;

    const float* qbase = qkv + (size_t)(b * 576 +       h * 32) * HW;
    const float* kbase = qkv + (size_t)(b * 576 + 192 + h * 32) * HW;
    const float* vbase = qkv + (size_t)(b * 576 + 384 + h * 32) * HW;

    for (int e = tid; e < 2048; e += 256) {
        int d  = e >> 6;
        int pi = (e >> 3) & 7;
        int pj = e & 7;
        buf[(pi * 8 + pj) * BFS + d] = qbase[(size_t)d * HW + (i0 + pi) * WID + (j0 + pj)];
    }
    for (int e = tid; e < 6272; e += 256) {
        int d = e / 196;
        int p = e % 196;
        kv_s[p * KVS + d] = kbase[(size_t)d * HW + (r0 + p / 14) * WID + (c0 + p % 14)];
    }
    for (int e = tid; e < 169; e += 256) rpb_s[e] = rpb[h * 169 + e];
    __syncthreads();

    if (tid < 196) {
        float4* r = reinterpret_cast<float4*>(&kv_s[tid * KVS]);
        float ss = 0.f;
#pragma unroll
        for (int t = 0; t < 8; t++) {
            float4 v = r[t];
            ss += v.x * v.x + v.y * v.y + v.z * v.z + v.w * v.w;
        }
        float sc = 1.f / fmaxf(sqrtf(ss), 1e-12f);
#pragma unroll
        for (int t = 0; t < 8; t++) {
            float4 v = r[t];
            r[t] = make_float4(v.x * sc, v.y * sc, v.z * sc, v.w * sc);
        }
    }
    if (tid < 64) {
        float4* r = reinterpret_cast<float4*>(&buf[tid * BFS]);
        float ss = 0.f;
#pragma unroll
        for (int t = 0; t < 8; t++) {
            float4 v = r[t];
            ss += v.x * v.x + v.y * v.y + v.z * v.z + v.w * v.w;
        }
        float sc = 1.f / fmaxf(sqrtf(ss), 1e-12f);
#pragma unroll
        for (int t = 0; t < 8; t++) {
            float4 v = r[t];
            r[t] = make_float4(v.x * sc, v.y * sc, v.z * sc, v.w * sc);
        }
    }
    __syncthreads();

    const int i  = i0 + w;
    const int si = min(max(i - 3, 0), 57);
    const float tscale = temp[h];

    const int ki1 = lane / 7, kj1 = lane % 7;
    const int ki2 = (lane + 32) / 7, kj2 = (lane + 32) % 7;
    const bool has2 = (lane < 17);

    const int rowBase = (si - r0) * 14;
    const int riOff   = si - i + 6;
    const int kOff1 = ki1 * 14 + kj1;
    const int kOff2 = ki2 * 14 + kj2;
    const int rb1   = (riOff + ki1) * 13 + kj1;
    const int rb2   = (riOff + ki2) * 13 + kj2;

#pragma unroll
    for (int px = 0; px < 8; px++) {
        const int j  = j0 + px;
        const int sj = min(max(j - 3, 0), 57);
        const int base  = rowBase + (sj - c0);
        const int cjOff = sj - j + 6;
        const int o1 = base + kOff1;
        const int o2 = has2 ? (base + kOff2) : 0;

        const ulonglong2* qp = reinterpret_cast<const ulonglong2*>(&buf[(w * 8 + px) * BFS]);
        const ulonglong2* k1 = reinterpret_cast<const ulonglong2*>(&kv_s[o1 * KVS]);
        const ulonglong2* k2 = reinterpret_cast<const ulonglong2*>(&kv_s[o2 * KVS]);

        unsigned long long s1p = 0ull, s2p = 0ull;
#pragma unroll
        for (int kd = 0; kd < 8; kd++) {
            ulonglong2 q2 = qp[kd];
            ulonglong2 a2 = k1[kd];
            ulonglong2 c2 = k2[kd];
            FMA2(s1p, q2.x, a2.x); FMA2(s1p, q2.y, a2.y);
            FMA2(s2p, q2.x, c2.x); FMA2(s2p, q2.y, c2.y);
        }
        float s1 = f2lo(s1p) + f2hi(s1p);
        float s2 = f2lo(s2p) + f2hi(s2p);

        s1 = (s1 + rpb_s[rb1 + cjOff]) * tscale;
        s2 = has2 ? (s2 + rpb_s[rb2 + cjOff]) * tscale : -1e30f;

        float m = fmaxf(s1, s2);
#pragma unroll
        for (int o = 16; o > 0; o >>= 1) m = fmaxf(m, __shfl_xor_sync(0xffffffffu, m, o));
        float e1 = __expf(s1 - m);
        float e2 = has2 ? __expf(s2 - m) : 0.f;
        float sm = e1 + e2;
#pragma unroll
        for (int o = 16; o > 0; o >>= 1) sm += __shfl_xor_sync(0xffffffffu, sm, o);
        float inv = 1.f / sm;
        buf[(w * 8 + px) * BFS + lane] = e1 * inv;
        if (has2) buf[(w * 8 + px) * BFS + lane + 32] = e2 * inv;
    }
    __syncthreads();

    for (int e = tid; e < 6272; e += 256) {
        int d = e / 196;
        int p = e % 196;
        kv_s[p * KVS + d] = vbase[(size_t)d * HW + (r0 + p / 14) * WID + (c0 + p % 14)];
    }
    __syncthreads();

    {
        const int oct = lane >> 3;
        const int dl  = lane & 7;
#pragma unroll
        for (int pass = 0; pass < 2; pass++) {
            const int px = pass * 4 + oct;
            const int j  = j0 + px;
            const int sj = min(max(j - 3, 0), 57);
            const int base = rowBase + (sj - c0);
            const float* pp = &buf[(w * 8 + px) * BFS];

            unsigned long long acc0 = 0ull, acc1 = 0ull;
            const float* vrow = &kv_s[base * KVS];
            int n = 0;
#pragma unroll
            for (int ki = 0; ki < 7; ki++) {
#pragma unroll
                for (int kj = 0; kj < 7; kj++) {
                    float p = pp[n++];
                    unsigned long long pd;
                    DUP2(pd, p);
                    ulonglong2 v2 = reinterpret_cast<const ulonglong2*>(vrow + kj * KVS)[dl];
                    FMA2(acc0, pd, v2.x);
                    FMA2(acc1, pd, v2.y);
                }
                vrow += 14 * KVS;
            }
            float4 o;
            o.x = f2lo(acc0); o.y = f2hi(acc0);
            o.z = f2lo(acc1); o.w = f2hi(acc1);
            reinterpret_cast<float4*>(&buf[(w * 8 + px) * BFS])[dl] = o;
        }
    }
    __syncthreads();

    for (int e = tid; e < 2048; e += 256) {
        int d  = e >> 6;
        int pi = (e >> 3) & 7;
        int pj = e & 7;
        outp[(size_t)(b * 192 + h * 32 + d) * HW + (i0 + pi) * WID + (j0 + pj)] =
            buf[(pi * 8 + pj) * BFS + d];
    }
}

// ---------------------------------------------------------------------------
extern "C" void kernel_launch(void* const* d_in, const int* in_sizes, int n_in,
                              void* d_out, int out_size)
{
    const float* x    = (const float*)d_in[0];
    const float* W1   = (const float*)d_in[1];
    const float* b1   = (const float*)d_in[2];
    const float* W2   = (const float*)d_in[3];
    const float* b2   = (const float*)d_in[4];
    const float* temp = (const float*)d_in[5];
    const float* rpb  = (const float*)d_in[6];
    const float* Wp   = (const float*)d_in[7];
    const float* bp   = (const float*)d_in[8];
    float* out = (float*)d_out;

    float *qkv1p, *qkv2p, *attp;
    cudaGetSymbolAddress((void**)&qkv1p, g_qkv1);
    cudaGetSymbolAddress((void**)&qkv2p, g_qkv2);
    cudaGetSymbolAddress((void**)&attp,  g_att);

    // 1) qkv 1x1 conv: [576x192]@[192x4096] per batch
    gemm_bias_kernel<<<dim3(32, 9, 2), 128>>>(W1, x, b1, qkv1p, 576, 192, 4096);

    // 2) depthwise 3x3 (smem-tiled per plane)
    dwconv_kernel<<<1152, 256>>>(qkv1p, W2, b2, qkv2p);

    // 3) neighborhood attention (l2norm fused)
    natten_kernel<<<dim3(8, 8, 12), 256>>>(qkv2p, rpb, temp, attp);

    // 4) projection 1x1 conv: split-K=2 + atomic accumulate onto zeroed out
    cudaMemsetAsync(out, 0, (size_t)out_size * sizeof(float));
    gemm_bias_splitk_kernel<<<dim3(32, 3, 4), 128>>>(Wp, attp, bp, out, 192, 192, 4096);
}